// round 1
// baseline (speedup 1.0000x reference)
#include <cuda_runtime.h>
#include <cstdint>

// ---------------------------------------------------------------------------
// WindowAttention3D: B=768, N=144, C=512, H=16, hd=32, NW=96
// Round 1: TF32 mma.sync everywhere, fp32 softmax.
// ---------------------------------------------------------------------------

#define B_TOT   768
#define NTOK    144
#define DIMC    512
#define NH      16
#define HD      32
#define NWIN    96
#define SCALE   0.17677669529663687f   // 1/sqrt(32)
#define NTOK2   (NTOK*NTOK)            // 20736
#define BHSTRIDE (NTOK*HD)             // 4608

// Scratch (device globals; allocation-free rule)
__device__ float g_qkv[3u*768u*16u*144u*32u];   // [3][B][H][N][hd]
__device__ float g_ctx[768u*144u*512u];         // [B][N][C]
__device__ float g_bias[16u*144u*144u];         // [H][N][N]

// ---------------------------------------------------------------------------
// helpers: tf32 convert + m16n8k8 mma
// ---------------------------------------------------------------------------
__device__ __forceinline__ uint32_t f2tf(float x) {
    uint32_t r;
    asm("cvt.rna.tf32.f32 %0, %1;" : "=r"(r) : "f"(x));
    return r;
}

__device__ __forceinline__ void mma_tf32(float* c, const uint32_t* a, const uint32_t* b) {
    asm volatile(
        "mma.sync.aligned.m16n8k8.row.col.f32.tf32.tf32.f32 "
        "{%0,%1,%2,%3},{%4,%5,%6,%7},{%8,%9},{%0,%1,%2,%3};\n"
        : "+f"(c[0]), "+f"(c[1]), "+f"(c[2]), "+f"(c[3])
        : "r"(a[0]), "r"(a[1]), "r"(a[2]), "r"(a[3]), "r"(b[0]), "r"(b[1]));
}

// ---------------------------------------------------------------------------
// Kernel 0: expand relative position bias table -> g_bias[h][n][m]
// ---------------------------------------------------------------------------
__global__ __launch_bounds__(256) void bias_expand_kernel(
    const float* __restrict__ table, const int* __restrict__ rel)
{
    int i = blockIdx.x * 256 + threadIdx.x;
    const int total = NH * NTOK2;
    if (i >= total) return;
    int h  = i / NTOK2;
    int nm = i - h * NTOK2;
    g_bias[i] = table[rel[nm] * NH + h];
}

// ---------------------------------------------------------------------------
// Kernel 1/3: TF32 GEMM  Out[m,n] = sum_k A[m,k] * W[n,k] + bias[n]
// M = 110592 fixed, K = 512 fixed. BM=128, BN=64, BK=16, 256 threads.
// MODE 0: QKV (Ncols=1536) scatter into g_qkv. MODE 1: proj (Ncols=512) to Out.
// ---------------------------------------------------------------------------
template <int MODE>
__global__ __launch_bounds__(256) void gemm_tf32_kernel(
    const float* __restrict__ A, const float* __restrict__ W,
    const float* __restrict__ bias, float* __restrict__ Out, int Ncols)
{
    __shared__ float As[128][20];
    __shared__ float Bs[64][20];

    const int nTiles = Ncols >> 6;
    const int m_tile = blockIdx.x / nTiles;
    const int n_tile = blockIdx.x - m_tile * nTiles;
    const int m0 = m_tile * 128, n0 = n_tile * 64;

    const int tid  = threadIdx.x;
    const int warp = tid >> 5, lane = tid & 31;
    const int wm = warp >> 1;     // 0..3  (32 rows each)
    const int wn = warp & 1;      // 0..1  (32 cols each)
    const int gm = lane >> 2, gk = lane & 3;

    const float* Aptr = (MODE == 0 ? A : g_ctx) + (size_t)m0 * DIMC;
    const float* Wptr = W + (size_t)n0 * DIMC;

    float acc[2][4][4];
    #pragma unroll
    for (int i = 0; i < 2; i++)
        #pragma unroll
        for (int j = 0; j < 4; j++)
            #pragma unroll
            for (int l = 0; l < 4; l++) acc[i][j][l] = 0.f;

    for (int k0 = 0; k0 < DIMC; k0 += 16) {
        __syncthreads();
        // load A tile 128x16
        #pragma unroll
        for (int r = 0; r < 2; r++) {
            int lin = r * 256 + tid;
            int row = lin >> 2, cv = (lin & 3) << 2;
            float4 t = *(const float4*)(Aptr + (size_t)row * DIMC + k0 + cv);
            *(float4*)&As[row][cv] = t;
        }
        // load B tile 64x16
        {
            int row = tid >> 2, cv = (tid & 3) << 2;
            float4 t = *(const float4*)(Wptr + (size_t)row * DIMC + k0 + cv);
            *(float4*)&Bs[row][cv] = t;
        }
        __syncthreads();

        #pragma unroll
        for (int kk = 0; kk < 16; kk += 8) {
            uint32_t afr[2][4], bfr[4][2];
            #pragma unroll
            for (int im = 0; im < 2; im++) {
                int rb = wm * 32 + im * 16;
                afr[im][0] = f2tf(As[rb + gm    ][kk + gk    ]);
                afr[im][1] = f2tf(As[rb + gm + 8][kk + gk    ]);
                afr[im][2] = f2tf(As[rb + gm    ][kk + gk + 4]);
                afr[im][3] = f2tf(As[rb + gm + 8][kk + gk + 4]);
            }
            #pragma unroll
            for (int in = 0; in < 4; in++) {
                int cb = wn * 32 + in * 8;
                bfr[in][0] = f2tf(Bs[cb + gm][kk + gk    ]);
                bfr[in][1] = f2tf(Bs[cb + gm][kk + gk + 4]);
            }
            #pragma unroll
            for (int im = 0; im < 2; im++)
                #pragma unroll
                for (int in = 0; in < 4; in++)
                    mma_tf32(acc[im][in], afr[im], bfr[in]);
        }
    }

    // store
    #pragma unroll
    for (int im = 0; im < 2; im++) {
        #pragma unroll
        for (int half = 0; half < 2; half++) {
            int rg = m0 + wm * 32 + im * 16 + gm + half * 8;
            int b_idx = rg / NTOK;
            int ntk   = rg - b_idx * NTOK;
            #pragma unroll
            for (int in = 0; in < 4; in++) {
                int cg = n0 + wn * 32 + in * 8 + gk * 2;
                float v0 = acc[im][in][half * 2 + 0] + bias[cg];
                float v1 = acc[im][in][half * 2 + 1] + bias[cg + 1];
                if (MODE == 0) {
                    int which = cg >> 9;
                    int rem   = cg & 511;
                    int h     = rem >> 5;
                    int d     = rem & 31;
                    size_t dst = ((size_t)(which * B_TOT + b_idx) * NH + h) * BHSTRIDE
                               + (size_t)ntk * HD + d;
                    *(float2*)&g_qkv[dst] = make_float2(v0, v1);
                } else {
                    *(float2*)&Out[(size_t)rg * DIMC + cg] = make_float2(v0, v1);
                }
            }
        }
    }
}

// ---------------------------------------------------------------------------
// Kernel 2: attention per (b,h). 256 threads, 143KB dyn smem.
//   S = scale*q@k^T + bias[h] + mask[b%96]; softmax rows; O = P@v -> g_ctx
// ---------------------------------------------------------------------------
#define SQ_STRIDE 36
#define SS_STRIDE 146
#define ATTN_SMEM ((3 * NTOK * SQ_STRIDE + NTOK * SS_STRIDE) * 4)

__global__ __launch_bounds__(256) void attn_kernel(const float* __restrict__ mask)
{
    extern __shared__ float sm[];
    float* sq = sm;
    float* sk = sq + NTOK * SQ_STRIDE;
    float* sv = sk + NTOK * SQ_STRIDE;
    float* sS = sv + NTOK * SQ_STRIDE;

    const int bh = blockIdx.x;
    const int b  = bh >> 4, h = bh & 15;
    const int w  = b % NWIN;

    const int tid  = threadIdx.x;
    const int warp = tid >> 5, lane = tid & 31;
    const int gm = lane >> 2, gk = lane & 3;

    const size_t qbase = ((size_t)(0 * B_TOT + b) * NH + h) * BHSTRIDE;
    const size_t kbase = ((size_t)(1 * B_TOT + b) * NH + h) * BHSTRIDE;
    const size_t vbase = ((size_t)(2 * B_TOT + b) * NH + h) * BHSTRIDE;

    // load q,k,v tiles [144][32] into padded smem
    for (int i = tid; i < (NTOK * HD / 4); i += 256) {
        int row = i >> 3;
        int d   = (i & 7) << 2;
        *(float4*)&sq[row * SQ_STRIDE + d] = *(const float4*)&g_qkv[qbase + (size_t)row * HD + d];
        *(float4*)&sk[row * SQ_STRIDE + d] = *(const float4*)&g_qkv[kbase + (size_t)row * HD + d];
        *(float4*)&sv[row * SQ_STRIDE + d] = *(const float4*)&g_qkv[vbase + (size_t)row * HD + d];
    }
    __syncthreads();

    const float* biasp = g_bias + (size_t)h * NTOK2;
    const float* maskp = mask   + (size_t)w * NTOK2;

    // ---- S = scale * q @ k^T + bias + mask ----
    for (int t = warp; t < 9 * 18; t += 8) {
        int mi = t / 18, ni = t - mi * 18;
        float acc[4] = {0.f, 0.f, 0.f, 0.f};
        #pragma unroll
        for (int k8 = 0; k8 < 4; k8++) {
            int d0 = k8 * 8;
            uint32_t a[4], bb[2];
            int rb = mi * 16;
            a[0] = f2tf(sq[(rb + gm    ) * SQ_STRIDE + d0 + gk    ]);
            a[1] = f2tf(sq[(rb + gm + 8) * SQ_STRIDE + d0 + gk    ]);
            a[2] = f2tf(sq[(rb + gm    ) * SQ_STRIDE + d0 + gk + 4]);
            a[3] = f2tf(sq[(rb + gm + 8) * SQ_STRIDE + d0 + gk + 4]);
            bb[0] = f2tf(sk[(ni * 8 + gm) * SQ_STRIDE + d0 + gk    ]);
            bb[1] = f2tf(sk[(ni * 8 + gm) * SQ_STRIDE + d0 + gk + 4]);
            mma_tf32(acc, a, bb);
        }
        #pragma unroll
        for (int half = 0; half < 2; half++) {
            int r = mi * 16 + gm + half * 8;
            int c = ni * 8 + gk * 2;
            float2 bv = *(const float2*)&biasp[r * NTOK + c];
            float2 mv = *(const float2*)&maskp[r * NTOK + c];
            float2 o;
            o.x = acc[half * 2 + 0] * SCALE + bv.x + mv.x;
            o.y = acc[half * 2 + 1] * SCALE + bv.y + mv.y;
            *(float2*)&sS[r * SS_STRIDE + c] = o;
        }
    }
    __syncthreads();

    // ---- row softmax ----
    if (tid < NTOK) {
        float* row = &sS[tid * SS_STRIDE];
        float mx = -1e30f;
        for (int j = 0; j < NTOK; j++) mx = fmaxf(mx, row[j]);
        float s = 0.f;
        for (int j = 0; j < NTOK; j++) { float e = __expf(row[j] - mx); row[j] = e; s += e; }
        float inv = 1.f / s;
        for (int j = 0; j < NTOK; j++) row[j] *= inv;
    }
    __syncthreads();

    // ---- O = P @ v  -> g_ctx[b, n, h*32 + d] ----
    const size_t obase = (size_t)b * NTOK * DIMC + (size_t)h * HD;
    for (int t = warp; t < 9 * 4; t += 8) {
        int mi = t >> 2, nd = t & 3;
        float acc[4] = {0.f, 0.f, 0.f, 0.f};
        #pragma unroll
        for (int k8 = 0; k8 < 18; k8++) {
            int k0 = k8 * 8;
            uint32_t a[4], bb[2];
            int rb = mi * 16;
            a[0] = f2tf(sS[(rb + gm    ) * SS_STRIDE + k0 + gk    ]);
            a[1] = f2tf(sS[(rb + gm + 8) * SS_STRIDE + k0 + gk    ]);
            a[2] = f2tf(sS[(rb + gm    ) * SS_STRIDE + k0 + gk + 4]);
            a[3] = f2tf(sS[(rb + gm + 8) * SS_STRIDE + k0 + gk + 4]);
            bb[0] = f2tf(sv[(k0 + gk    ) * SQ_STRIDE + nd * 8 + gm]);
            bb[1] = f2tf(sv[(k0 + gk + 4) * SQ_STRIDE + nd * 8 + gm]);
            mma_tf32(acc, a, bb);
        }
        #pragma unroll
        for (int half = 0; half < 2; half++) {
            int r = mi * 16 + gm + half * 8;
            int dc = nd * 8 + gk * 2;
            *(float2*)&g_ctx[obase + (size_t)r * DIMC + dc] =
                make_float2(acc[half * 2 + 0], acc[half * 2 + 1]);
        }
    }
}

// ---------------------------------------------------------------------------
// launch
// ---------------------------------------------------------------------------
extern "C" void kernel_launch(void* const* d_in, const int* in_sizes, int n_in,
                              void* d_out, int out_size)
{
    const float* x      = (const float*)d_in[0];
    const float* mask   = (const float*)d_in[1];
    const float* qkv_w  = (const float*)d_in[2];
    const float* qkv_b  = (const float*)d_in[3];
    const float* proj_w = (const float*)d_in[4];
    const float* proj_b = (const float*)d_in[5];
    const float* table  = (const float*)d_in[6];
    const int*   rel    = (const int*)d_in[7];
    float* out = (float*)d_out;

    // 0: bias expand
    bias_expand_kernel<<<(NH * NTOK2 + 255) / 256, 256>>>(table, rel);

    // 1: QKV GEMM (M=110592, N=1536) -> g_qkv
    gemm_tf32_kernel<0><<<864 * 24, 256>>>(x, qkv_w, qkv_b, nullptr, 1536);

    // 2: attention
    cudaFuncSetAttribute(attn_kernel, cudaFuncAttributeMaxDynamicSharedMemorySize, ATTN_SMEM);
    attn_kernel<<<B_TOT * NH, 256, ATTN_SMEM>>>(mask);

    // 3: proj GEMM (M=110592, N=512) -> out
    gemm_tf32_kernel<1><<<864 * 8, 256>>>(nullptr, proj_w, proj_b, out, 512);
}